// round 7
// baseline (speedup 1.0000x reference)
#include <cuda_runtime.h>

// OTTT step: s, u_new = LIF(sig_tau*u + x@W + b); a_hat_new = sig_tau*a_hat + x
// Inputs (metadata order): W [8192*8192] f32, b [8192], u [8192], a_hat [8192], x [8192]
// Output: flat [s(8192) | u_new(8192) | a_hat_new(8192)] f32
//
// Single kernel, full-K per CTA: 256 CTAs x 32 columns, no split-K partials,
// no second kernel, no DRAM round-trip. Epilogue fused in-CTA.

#define IN_DIM  8192
#define OUT_DIM 8192
#define TPB     256
#define CW      32                         // columns per CTA
#define C4W     (CW / 4)                   // 8 float4 columns per CTA
#define PHASES  32                         // row phases (threads per column)
#define RPT     (IN_DIM / PHASES)          // 256 rows per thread
#define NBLK    (OUT_DIM / CW)             // 256 CTAs

// sigmoid(2.0)
#define SIG_TAU 0.8807970779778823f
#define V_TH    1.0f

__global__ void __launch_bounds__(TPB) ottt_step(
    const float* __restrict__ W, const float* __restrict__ x,
    const float* __restrict__ b, const float* __restrict__ u,
    const float* __restrict__ a_hat, float* __restrict__ out)
{
    const int t  = threadIdx.x;
    const int c  = t & (C4W - 1);          // float4 column 0..7
    const int g  = t >> 3;                 // row phase 0..31
    const int c4 = blockIdx.x * C4W + c;   // global float4 column index

    __shared__ float  xs[IN_DIM];          // 32 KB
    __shared__ float4 red[PHASES][C4W];    // 4 KB

    // stage x once (coalesced float4)
    {
        const float4* __restrict__ xv4 = reinterpret_cast<const float4*>(x);
        float4* __restrict__ xs4 = reinterpret_cast<float4*>(xs);
        #pragma unroll
        for (int i = 0; i < IN_DIM / 4 / TPB; ++i)
            xs4[t + i * TPB] = xv4[t + i * TPB];
    }
    __syncthreads();

    // main loop: thread (c,g) accumulates rows g, g+32, g+64, ...
    const float4* __restrict__ Wv = reinterpret_cast<const float4*>(W);
    const size_t row_v4 = OUT_DIM / 4;

    float ax = 0.f, ay = 0.f, az = 0.f, aw = 0.f;

    #pragma unroll 8
    for (int k = 0; k < RPT; ++k) {
        const int r = g + k * PHASES;
        // streaming load: W never reused — evict-first in L2
        float4 w = __ldcs(Wv + (size_t)r * row_v4 + c4);
        float xv = xs[r];
        ax = fmaf(xv, w.x, ax);
        ay = fmaf(xv, w.y, ay);
        az = fmaf(xv, w.z, az);
        aw = fmaf(xv, w.w, aw);
    }

    red[g][c] = make_float4(ax, ay, az, aw);
    __syncthreads();

    // stage 1: 32 -> 8 partials per column (fixed order, deterministic)
    if (t < 64) {
        const int cc = t & (C4W - 1);
        const int h  = t >> 3;             // 0..7
        float4 s0 = red[h][cc];
        #pragma unroll
        for (int k = 1; k < 4; ++k) {
            float4 p = red[h + 8 * k][cc];
            s0.x += p.x; s0.y += p.y; s0.z += p.z; s0.w += p.w;
        }
        red[h][cc] = s0;
    }
    __syncthreads();

    // stage 2 + fused epilogue: one thread per float4 column
    if (t < C4W) {
        float4 acc = red[0][t];
        #pragma unroll
        for (int h = 1; h < 8; ++h) {
            float4 p = red[h][t];
            acc.x += p.x; acc.y += p.y; acc.z += p.z; acc.w += p.w;
        }

        const int  cg = blockIdx.x * C4W + t;
        const float4 bv = reinterpret_cast<const float4*>(b)[cg];
        const float4 uv = reinterpret_cast<const float4*>(u)[cg];

        float4 upre, sv, unew;
        upre.x = fmaf(SIG_TAU, uv.x, acc.x + bv.x);
        upre.y = fmaf(SIG_TAU, uv.y, acc.y + bv.y);
        upre.z = fmaf(SIG_TAU, uv.z, acc.z + bv.z);
        upre.w = fmaf(SIG_TAU, uv.w, acc.w + bv.w);
        sv.x = (upre.x >= V_TH) ? 1.0f : 0.0f;
        sv.y = (upre.y >= V_TH) ? 1.0f : 0.0f;
        sv.z = (upre.z >= V_TH) ? 1.0f : 0.0f;
        sv.w = (upre.w >= V_TH) ? 1.0f : 0.0f;
        unew.x = upre.x - sv.x * V_TH;
        unew.y = upre.y - sv.y * V_TH;
        unew.z = upre.z - sv.z * V_TH;
        unew.w = upre.w - sv.w * V_TH;

        reinterpret_cast<float4*>(out)[cg]           = sv;
        reinterpret_cast<float4*>(out + OUT_DIM)[cg] = unew;

        // a_hat_new = sig_tau*a_hat + x (IN_DIM == OUT_DIM, same column range;
        // x for these columns is already staged in xs)
        const float4 av = reinterpret_cast<const float4*>(a_hat)[cg];
        const float4 xv = reinterpret_cast<const float4*>(xs)[cg];
        float4 an;
        an.x = fmaf(SIG_TAU, av.x, xv.x);
        an.y = fmaf(SIG_TAU, av.y, xv.y);
        an.z = fmaf(SIG_TAU, av.z, xv.z);
        an.w = fmaf(SIG_TAU, av.w, xv.w);
        reinterpret_cast<float4*>(out + 2 * OUT_DIM)[cg] = an;
    }
}

extern "C" void kernel_launch(void* const* d_in, const int* in_sizes, int n_in,
                              void* d_out, int out_size)
{
    const float* W     = (const float*)d_in[0];
    const float* b     = (const float*)d_in[1];
    const float* u     = (const float*)d_in[2];
    const float* a_hat = (const float*)d_in[3];
    const float* x     = (const float*)d_in[4];
    float* out = (float*)d_out;

    ottt_step<<<NBLK, TPB>>>(W, x, b, u, a_hat, out);
}

// round 8
// speedup vs baseline: 1.3848x; 1.3848x over previous
#include <cuda_runtime.h>

// OTTT step: s, u_new = LIF(sig_tau*u + x@W + b); a_hat_new = sig_tau*a_hat + x
// Inputs (metadata order): W [8192*8192] f32, b [8192], u [8192], a_hat [8192], x [8192]
// Output: flat [s(8192) | u_new(8192) | a_hat_new(8192)] f32
//
// Split-K GEMV (proven 6.8 TB/s shape) + PDL-overlapped epilogue.

#define IN_DIM  8192
#define OUT_DIM 8192
#define SPLITS  64
#define ROWS_PER_SPLIT (IN_DIM / SPLITS)   // 128
#define TPB     256
#define JPT     4                          // columns per thread (float4)
#define JPB     (TPB * JPT)                // 1024 columns per block
#define JBLOCKS (OUT_DIM / JPB)            // 8

// sigmoid(2.0)
#define SIG_TAU 0.8807970779778823f
#define V_TH    1.0f

// split-K partial sums (2 MB scratch; __device__ global per allocation rules)
__device__ float g_part[(size_t)SPLITS * OUT_DIM];

__global__ void __launch_bounds__(TPB) gemv_partial(
    const float* __restrict__ W, const float* __restrict__ x)
{
    const int jb    = blockIdx.x;           // 0..7
    const int split = blockIdx.y;           // 0..63
    const int j0    = jb * JPB + threadIdx.x * JPT;
    const int i0    = split * ROWS_PER_SPLIT;

    __shared__ float xs[ROWS_PER_SPLIT];
    for (int t = threadIdx.x; t < ROWS_PER_SPLIT; t += TPB)
        xs[t] = x[i0 + t];
    __syncthreads();

    const float4* __restrict__ Wv =
        reinterpret_cast<const float4*>(W + (size_t)i0 * OUT_DIM + j0);
    const size_t row_stride_v4 = OUT_DIM / 4;

    float ax = 0.f, ay = 0.f, az = 0.f, aw = 0.f;

    #pragma unroll 8
    for (int r = 0; r < ROWS_PER_SPLIT; ++r) {
        // streaming load: W is 268MB, never reused — evict-first in L2
        float4 w = __ldcs(Wv + (size_t)r * row_stride_v4);
        float xv = xs[r];
        ax = fmaf(xv, w.x, ax);
        ay = fmaf(xv, w.y, ay);
        az = fmaf(xv, w.z, az);
        aw = fmaf(xv, w.w, aw);
    }

    float4 acc = make_float4(ax, ay, az, aw);
    *reinterpret_cast<float4*>(g_part + (size_t)split * OUT_DIM + j0) = acc;

    // allow the dependent epilogue grid to begin launching/prefetching;
    // partial visibility is guaranteed by its cudaGridDependencySynchronize().
    cudaTriggerProgrammaticLaunchCompletion();
}

// Epilogue (PDL secondary): one warp per float4 column, 2048 warps.
// Pre-sync: load all GEMV-independent vectors and write a_hat output.
// Post-sync: 2 partial loads/lane, butterfly shfl reduce (deterministic), LIF.
#define EPI_TPB    256
#define EPI_BLOCKS (OUT_DIM / 4 / (EPI_TPB / 32))   // 256

__global__ void __launch_bounds__(EPI_TPB) lif_epilogue(
    const float* __restrict__ b, const float* __restrict__ u,
    const float* __restrict__ a_hat, const float* __restrict__ x,
    float* __restrict__ out)
{
    const int warp = (blockIdx.x * EPI_TPB + threadIdx.x) >> 5;  // 0..2047
    const int lane = threadIdx.x & 31;
    const int c4   = warp;                       // float4 column index

    // ---- independent work before waiting on the GEMV ----
    float4 bv = make_float4(0.f, 0.f, 0.f, 0.f);
    float4 uv = bv;
    if (lane == 0) {
        bv = reinterpret_cast<const float4*>(b)[c4];
        uv = reinterpret_cast<const float4*>(u)[c4];
    } else if (lane == 1) {
        // a_hat_new = sig_tau*a_hat + x (IN_DIM == OUT_DIM, same column range)
        const float4 av = reinterpret_cast<const float4*>(a_hat)[c4];
        const float4 xv = reinterpret_cast<const float4*>(x)[c4];
        float4 an;
        an.x = fmaf(SIG_TAU, av.x, xv.x);
        an.y = fmaf(SIG_TAU, av.y, xv.y);
        an.z = fmaf(SIG_TAU, av.z, xv.z);
        an.w = fmaf(SIG_TAU, av.w, xv.w);
        reinterpret_cast<float4*>(out + 2 * OUT_DIM)[c4] = an;
    }

    // ---- wait for the GEMV grid's memory to be visible ----
    cudaGridDependencySynchronize();

    const float4* __restrict__ Pv = reinterpret_cast<const float4*>(g_part);
    const size_t row_v4 = OUT_DIM / 4;

    float4 p0 = Pv[(size_t)lane * row_v4 + c4];
    float4 p1 = Pv[(size_t)(lane + 32) * row_v4 + c4];
    float4 t;
    t.x = p0.x + p1.x; t.y = p0.y + p1.y;
    t.z = p0.z + p1.z; t.w = p0.w + p1.w;

    #pragma unroll
    for (int off = 16; off > 0; off >>= 1) {
        t.x += __shfl_xor_sync(0xffffffffu, t.x, off);
        t.y += __shfl_xor_sync(0xffffffffu, t.y, off);
        t.z += __shfl_xor_sync(0xffffffffu, t.z, off);
        t.w += __shfl_xor_sync(0xffffffffu, t.w, off);
    }

    if (lane == 0) {
        float4 upre, sv, unew;
        upre.x = fmaf(SIG_TAU, uv.x, t.x + bv.x);
        upre.y = fmaf(SIG_TAU, uv.y, t.y + bv.y);
        upre.z = fmaf(SIG_TAU, uv.z, t.z + bv.z);
        upre.w = fmaf(SIG_TAU, uv.w, t.w + bv.w);
        sv.x = (upre.x >= V_TH) ? 1.0f : 0.0f;
        sv.y = (upre.y >= V_TH) ? 1.0f : 0.0f;
        sv.z = (upre.z >= V_TH) ? 1.0f : 0.0f;
        sv.w = (upre.w >= V_TH) ? 1.0f : 0.0f;
        unew.x = upre.x - sv.x * V_TH;
        unew.y = upre.y - sv.y * V_TH;
        unew.z = upre.z - sv.z * V_TH;
        unew.w = upre.w - sv.w * V_TH;

        reinterpret_cast<float4*>(out)[c4]           = sv;
        reinterpret_cast<float4*>(out + OUT_DIM)[c4] = unew;
    }
}

extern "C" void kernel_launch(void* const* d_in, const int* in_sizes, int n_in,
                              void* d_out, int out_size)
{
    const float* W     = (const float*)d_in[0];
    const float* b     = (const float*)d_in[1];
    const float* u     = (const float*)d_in[2];
    const float* a_hat = (const float*)d_in[3];
    const float* x     = (const float*)d_in[4];
    float* out = (float*)d_out;

    dim3 grid(JBLOCKS, SPLITS);
    gemv_partial<<<grid, TPB>>>(W, x);

    // PDL secondary: may launch while gemv_partial drains.
    cudaLaunchConfig_t cfg = {};
    cfg.gridDim  = dim3(EPI_BLOCKS, 1, 1);
    cfg.blockDim = dim3(EPI_TPB, 1, 1);
    cfg.dynamicSmemBytes = 0;
    cfg.stream = 0;
    cudaLaunchAttribute attr[1];
    attr[0].id = cudaLaunchAttributeProgrammaticStreamSerialization;
    attr[0].val.programmaticStreamSerializationAllowed = 1;
    cfg.attrs = attr;
    cfg.numAttrs = 1;
    cudaLaunchKernelEx(&cfg, lif_epilogue, b, u, a_hat, x, out);
}